// round 17
// baseline (speedup 1.0000x reference)
#include <cuda_runtime.h>

// Inputs (metadata order; reference int64 narrowed to int32 by harness):
//   d_in[0]: y      float32 (T, B, 7)
//   d_in[1]: t      int32   (T, B, 3)
//   d_in[2]: y_len  int32   (B,)
// Output: float32 scalar
//
// Block = one timestep t across all B=512 samples. TMA bulk-copies the
// block's contiguous y (14336B) + t (6144B) spans into SMEM (no L1tex
// per-lane wavefronts), then each thread reads its 4 samples via
// conflict-free LDS.128. Fixed-point int64 accumulation => deterministic.

#define TPB 128
#define FXP_SCALE 17592186044416.0  // 2^44

__device__ unsigned long long g_iacc = 0ull;
__device__ unsigned          g_count = 0u;

// Per-sample NLL with one log: log(s0*s1*s2) - (sel0+sel1+sel2).
__device__ __forceinline__ float ce_row(float l0, float l1, float l2,
                                        float l3, float l4,
                                        float l5, float l6,
                                        int c0, int c1, int c2)
{
    float s0 = __expf(l0) + __expf(l1) + __expf(l2);
    float s1 = __expf(l3) + __expf(l4);
    float s2 = __expf(l5) + __expf(l6);
    float sel0 = (c0 == 0) ? l0 : ((c0 == 1) ? l1 : l2);
    float sel1 = (c1 == 0) ? l3 : l4;
    float sel2 = (c2 == 0) ? l5 : l6;
    return __logf(s0 * s1 * s2) - (sel0 + sel1 + sel2);
}

// B=512 specialization: y span/block = 512*7 floats = 896 float4 (14336B),
// t span/block = 512*3 ints = 384 int4 (6144B).
__global__ __launch_bounds__(TPB)
void ce_loss_kernel_tma(const float4* __restrict__ y4,
                        const int4* __restrict__ t4,
                        const int4* __restrict__ len4,
                        float* __restrict__ out,
                        float qscale, unsigned nblocks)
{
    __shared__ __align__(128) float4 ys[896];
    __shared__ __align__(128) int4   tsm[384];
    __shared__ __align__(8) unsigned long long mbar;
    __shared__ float wsum[TPB / 32];

    const int t   = blockIdx.x;
    const int tid = threadIdx.x;

    const unsigned mbar_s = (unsigned)__cvta_generic_to_shared(&mbar);
    const unsigned ys_s   = (unsigned)__cvta_generic_to_shared(ys);
    const unsigned ts_s   = (unsigned)__cvta_generic_to_shared(tsm);

    if (tid == 0) {
        asm volatile("mbarrier.init.shared.b64 [%0], 1;" :: "r"(mbar_s) : "memory");
    }
    __syncthreads();

    if (tid == 0) {
        asm volatile("mbarrier.arrive.expect_tx.shared.b64 _, [%0], %1;"
                     :: "r"(mbar_s), "r"(14336u + 6144u) : "memory");
        const float4* ysrc = y4 + (size_t)t * 896;
        const int4*   tsrc = t4 + (size_t)t * 384;
        asm volatile("cp.async.bulk.shared::cta.global.mbarrier::complete_tx::bytes "
                     "[%0], [%1], %2, [%3];"
                     :: "r"(ys_s), "l"(ysrc), "r"(14336u), "r"(mbar_s) : "memory");
        asm volatile("cp.async.bulk.shared::cta.global.mbarrier::complete_tx::bytes "
                     "[%0], [%1], %2, [%3];"
                     :: "r"(ts_s), "l"(tsrc), "r"(6144u), "r"(mbar_s) : "memory");
    }

    // Overlap: fetch lengths while TMA is in flight.
    const int4 L = len4[tid];          // samples 4*tid..4*tid+3 (L2-resident)
    const int maxlen = max(max(L.x, L.y), max(L.z, L.w));

    // Wait for TMA completion (acquire orders the LDS reads below).
    {
        unsigned done;
        asm volatile(
            "{\n\t"
            ".reg .pred p;\n\t"
            "WAIT_%=: mbarrier.try_wait.parity.acquire.cta.shared::cta.b64 p, [%1], 0, 0x989680;\n\t"
            "@p bra DONE_%=;\n\t"
            "bra WAIT_%=;\n\t"
            "DONE_%=: mov.u32 %0, 1;\n\t"
            "}"
            : "=r"(done) : "r"(mbar_s) : "memory");
        (void)done;
    }

    float contrib = 0.0f;

    if (t < maxlen) {
        const int a0 = t < L.x;
        const int a1 = t < L.y;
        const int a2 = t < L.z;
        const int a3 = t < L.w;

        // Conflict-free LDS.128: group (7l+j)&7 / (3l+j)&7 are permutations.
        const float4* yb = ys  + tid * 7;
        const int4*   tb = tsm + tid * 3;
        float4 v0 = yb[0], v1 = yb[1], v2 = yb[2], v3 = yb[3];
        float4 v4 = yb[4], v5 = yb[5], v6 = yb[6];
        int4 i0 = tb[0], i1 = tb[1], i2 = tb[2];

        if (a0)
            contrib += __fdividef(
                ce_row(v0.x, v0.y, v0.z, v0.w, v1.x, v1.y, v1.z,
                       i0.x, i0.y, i0.z), (float)L.x);
        if (a1)
            contrib += __fdividef(
                ce_row(v1.w, v2.x, v2.y, v2.z, v2.w, v3.x, v3.y,
                       i0.w, i1.x, i1.y), (float)L.y);
        if (a2)
            contrib += __fdividef(
                ce_row(v3.z, v3.w, v4.x, v4.y, v4.z, v4.w, v5.x,
                       i1.z, i1.w, i2.x), (float)L.z);
        if (a3)
            contrib += __fdividef(
                ce_row(v5.y, v5.z, v5.w, v6.x, v6.y, v6.z, v6.w,
                       i2.y, i2.z, i2.w), (float)L.w);
    }

    // warp reduce (deterministic tree)
    #pragma unroll
    for (int off = 16; off > 0; off >>= 1)
        contrib += __shfl_down_sync(0xFFFFFFFFu, contrib, off);

    const int lane = tid & 31;
    const int wid  = tid >> 5;
    if (lane == 0) wsum[wid] = contrib;
    __syncthreads();

    if (tid == 0) {
        float v = wsum[0];
        #pragma unroll
        for (int w = 1; w < TPB / 32; ++w) v += wsum[w];

        // Deterministic fixed-point accumulation (associative integer adds).
        long long q = llrintf(v * qscale);
        unsigned long long old = atomicAdd(&g_iacc, (unsigned long long)q);
        unsigned dep = (unsigned)old;
        asm("and.b32 %0, %0, 0;" : "+r"(dep));     // un-foldable zeroing
        unsigned ticket = atomicAdd(&g_count, 1u + dep);

        if (ticket == nblocks - 1) {
            unsigned long long tot = atomicExch(&g_iacc, 0ull);
            out[0] = (float)((double)(long long)tot * (1.0 / FXP_SCALE));
            atomicExch(&g_count, 0u);               // reset for next replay
        }
    }
}

// Generic fallback (LDG path, runtime BG) for unexpected shapes.
__device__ __forceinline__ float4 ldp_f4(const float4* p, int pred) {
    float4 v;
    asm("{\n\t.reg .pred lp;\n\tsetp.ne.s32 lp, %5, 0;\n\t"
        "@lp ld.global.nc.v4.f32 {%0,%1,%2,%3}, [%4];\n\t}"
        : "=f"(v.x), "=f"(v.y), "=f"(v.z), "=f"(v.w)
        : "l"(p), "r"(pred));
    return v;
}
__device__ __forceinline__ int4 ldp_i4(const int4* p, int pred) {
    int4 v;
    asm("{\n\t.reg .pred lp;\n\tsetp.ne.s32 lp, %5, 0;\n\t"
        "@lp ld.global.nc.v4.u32 {%0,%1,%2,%3}, [%4];\n\t}"
        : "=r"(v.x), "=r"(v.y), "=r"(v.z), "=r"(v.w)
        : "l"(p), "r"(pred));
    return v;
}

__global__ __launch_bounds__(TPB)
void ce_loss_kernel_gen(const float4* __restrict__ y4,
                        const int4* __restrict__ t4,
                        const int4* __restrict__ len4,
                        float* __restrict__ out,
                        float qscale, unsigned nblocks, int BG)
{
    const int tid = blockIdx.x * TPB + threadIdx.x;
    const int t   = tid / BG;
    const int bg  = tid - t * BG;

    float contrib = 0.0f;
    const int4 L = len4[bg];
    const int maxlen = max(max(L.x, L.y), max(L.z, L.w));

    if (t < maxlen) {
        const int a0 = t < L.x, a1 = t < L.y, a2 = t < L.z, a3 = t < L.w;
        const float4* yb = y4 + tid * 7;
        const int4*   tb = t4 + tid * 3;
        float4 v0 = ldp_f4(yb + 0, a0);
        float4 v1 = ldp_f4(yb + 1, a0 | a1);
        float4 v2 = ldp_f4(yb + 2, a1);
        float4 v3 = ldp_f4(yb + 3, a1 | a2);
        float4 v4 = ldp_f4(yb + 4, a2);
        float4 v5 = ldp_f4(yb + 5, a2 | a3);
        float4 v6 = ldp_f4(yb + 6, a3);
        int4 i0 = ldp_i4(tb + 0, a0 | a1);
        int4 i1 = ldp_i4(tb + 1, a1 | a2);
        int4 i2 = ldp_i4(tb + 2, a2 | a3);
        if (a0) contrib += __fdividef(ce_row(v0.x, v0.y, v0.z, v0.w, v1.x, v1.y, v1.z,
                                             i0.x, i0.y, i0.z), (float)L.x);
        if (a1) contrib += __fdividef(ce_row(v1.w, v2.x, v2.y, v2.z, v2.w, v3.x, v3.y,
                                             i0.w, i1.x, i1.y), (float)L.y);
        if (a2) contrib += __fdividef(ce_row(v3.z, v3.w, v4.x, v4.y, v4.z, v4.w, v5.x,
                                             i1.z, i1.w, i2.x), (float)L.z);
        if (a3) contrib += __fdividef(ce_row(v5.y, v5.z, v5.w, v6.x, v6.y, v6.z, v6.w,
                                             i2.y, i2.z, i2.w), (float)L.w);
    }

    #pragma unroll
    for (int off = 16; off > 0; off >>= 1)
        contrib += __shfl_down_sync(0xFFFFFFFFu, contrib, off);

    __shared__ float wsum[TPB / 32];
    if ((threadIdx.x & 31) == 0) wsum[threadIdx.x >> 5] = contrib;
    __syncthreads();

    if (threadIdx.x == 0) {
        float v = wsum[0];
        #pragma unroll
        for (int w = 1; w < TPB / 32; ++w) v += wsum[w];
        long long q = llrintf(v * qscale);
        unsigned long long old = atomicAdd(&g_iacc, (unsigned long long)q);
        unsigned dep = (unsigned)old;
        asm("and.b32 %0, %0, 0;" : "+r"(dep));
        unsigned ticket = atomicAdd(&g_count, 1u + dep);
        if (ticket == nblocks - 1) {
            unsigned long long tot = atomicExch(&g_iacc, 0ull);
            out[0] = (float)((double)(long long)tot * (1.0 / FXP_SCALE));
            atomicExch(&g_count, 0u);
        }
    }
}

extern "C" void kernel_launch(void* const* d_in, const int* in_sizes, int n_in,
                              void* d_out, int out_size)
{
    const float4* y4   = (const float4*)d_in[0];
    const int4*   t4   = (const int4*)d_in[1];
    const int4*   len4 = (const int4*)d_in[2];
    float* out = (float*)d_out;

    const int B  = in_sizes[2];                // 512
    const int T  = in_sizes[0] / (B * 7);      // 4096
    const float qscale = (float)(FXP_SCALE / (double)B);

    if (B == 512) {
        // One block per timestep; TMA streams the block's contiguous spans.
        ce_loss_kernel_tma<<<T, TPB>>>(y4, t4, len4, out, qscale, (unsigned)T);
    } else {
        const int BG = B >> 2;
        const long long total = (long long)T * BG;
        const unsigned nblocks = (unsigned)((total + TPB - 1) / TPB);
        ce_loss_kernel_gen<<<nblocks, TPB>>>(y4, t4, len4, out, qscale, nblocks, BG);
    }
}